// round 6
// baseline (speedup 1.0000x reference)
#include <cuda_runtime.h>
#include <cstdint>

// ---------------- problem constants ----------------
#define D_DIM  512
#define HID    513
#define HIDP   576            // 12 * 48
#define P_CTX  8192
#define KTEST  2048
#define LDEPTH 8
#define HIDP2  (HIDP*HIDP)

#define TMW    48             // tile side
#define CH     16             // K per chunk
#define SST    52             // smem k-row stride (words)
#define NT12   12
#define NPR    78             // upper-tri 48-tile pairs (12x13/2)
#define SZ     3              // split-K for syrk
#define TEL    (TMW*TMW)      // 2304

// ---------------- scratch ----------------
__device__ float g_Part[NPR*SZ*TEL];
__device__ unsigned int g_cnt[NPR];       // zero-init
__device__ float g_S  [HIDP2];
__device__ float g_Wxa[HIDP2];
__device__ float g_WqT[HIDP2];
__device__ float g_WkT[HIDP2];
__device__ float g_WvP[HIDP2];
__device__ float g_F  [HIDP2];
__device__ float g_G  [HIDP2];
__device__ float g_T  [HIDP2];
__device__ float g_T2 [HIDP2];
__device__ float g_A  [LDEPTH*HIDP2];
__device__ float g_u  [2*HID];
__device__ float g_d  [D_DIM];

// ================= fp32 GEMM, 48x48 tile ====================================
// acc(m,n) = sum_k A[m,k]*B[n,k]   (both row-major, K contiguous)
// mode 0: C = alpha*acc   (direct write, grid 12x12, tile (by*48, bx*48))
// mode 1: C = Dm - acc    (direct write)
// mode 2: syrk of aug=[X|y]: blockIdx.x = pair, blockIdx.z = K-split;
//         partial -> g_Part, last CTA reduces + symmetric write into C (=S)
__global__ __launch_bounds__(256) void gemm48(
    const float* __restrict__ A, int lda,
    const float* __restrict__ B, int ldb,
    const float* __restrict__ yv,
    float* __restrict__ C, const float* __restrict__ Dm,
    float alpha, int mode)
{
    __shared__ float As[2][CH*SST];
    __shared__ float Bs[2][CH*SST];
    __shared__ int slast;
    const int tid = threadIdx.x;
    const int tx = tid & 15, ty = tid >> 4;

    int bm, bn, q = 0, z = 0, nch, kst0;
    if (mode == 2) {
        q = blockIdx.x;
        int ti = 0, rem = q;
        while (rem >= NT12 - ti) { rem -= NT12 - ti; ti++; }
        bm = ti * TMW; bn = (ti + rem) * TMW;
        z = blockIdx.z;
        kst0 = z * 171;                  // chunk units
        nch  = (z < 2) ? 171 : 170;      // 171+171+170 = 512 chunks = 8192
    } else {
        bm = blockIdx.y * TMW; bn = blockIdx.x * TMW;
        kst0 = 0; nch = HIDP / CH;       // 36
    }

    // loader thread mapping (threads 0..191 active)
    const bool ldr = tid < 192;
    const int am = tid >> 2, ak = (tid & 3) * 4;     // mode 0/1
    const int pl = tid / 12, sg = tid % 12;          // mode 2

    float4 va, vb;

    auto aug4 = [&](int c0, int p) -> float4 {
        if (c0 < D_DIM) return *(const float4*)(A + (size_t)p * D_DIM + c0);
        float4 v = {0.f, 0.f, 0.f, 0.f};
        if (c0 == D_DIM) v.x = yv[p];
        return v;
    };

    auto ldg = [&](int ch) {
        if (!ldr) return;
        const int k0 = (kst0 + ch) * CH;
        if (mode == 2) {
            const int p = k0 + pl;
            va = aug4(bm + sg * 4, p);
            vb = aug4(bn + sg * 4, p);
        } else {
            va = *(const float4*)(A + (size_t)(bm + am) * lda + k0 + ak);
            vb = *(const float4*)(B + (size_t)(bn + am) * ldb + k0 + ak);
        }
    };
    auto sts = [&](int buf) {
        if (!ldr) return;
        if (mode == 2) {
            *(float4*)&As[buf][pl * SST + sg * 4] = va;
            *(float4*)&Bs[buf][pl * SST + sg * 4] = vb;
        } else {
            As[buf][(ak + 0) * SST + am] = va.x;
            As[buf][(ak + 1) * SST + am] = va.y;
            As[buf][(ak + 2) * SST + am] = va.z;
            As[buf][(ak + 3) * SST + am] = va.w;
            Bs[buf][(ak + 0) * SST + am] = vb.x;
            Bs[buf][(ak + 1) * SST + am] = vb.y;
            Bs[buf][(ak + 2) * SST + am] = vb.z;
            Bs[buf][(ak + 3) * SST + am] = vb.w;
        }
    };

    float acc[3][3] = {};

    ldg(0);
    sts(0);
    __syncthreads();

    for (int ch = 0; ch < nch; ch++) {
        const int buf = ch & 1;
        const bool more = (ch + 1 < nch);
        if (more) ldg(ch + 1);

        const float* Ab = As[buf];
        const float* Bb = Bs[buf];
        #pragma unroll
        for (int k = 0; k < CH; k++) {
            const float a0 = Ab[k * SST + ty * 3 + 0];
            const float a1 = Ab[k * SST + ty * 3 + 1];
            const float a2 = Ab[k * SST + ty * 3 + 2];
            const float b0 = Bb[k * SST + tx * 3 + 0];
            const float b1 = Bb[k * SST + tx * 3 + 1];
            const float b2 = Bb[k * SST + tx * 3 + 2];
            acc[0][0] += a0 * b0; acc[0][1] += a0 * b1; acc[0][2] += a0 * b2;
            acc[1][0] += a1 * b0; acc[1][1] += a1 * b1; acc[1][2] += a1 * b2;
            acc[2][0] += a2 * b0; acc[2][1] += a2 * b1; acc[2][2] += a2 * b2;
        }

        if (more) {
            __syncthreads();
            sts(buf ^ 1);
            __syncthreads();
        }
    }

    if (mode != 2) {
        #pragma unroll
        for (int i = 0; i < 3; i++) {
            const size_t row = (size_t)(bm + ty * 3 + i) * HIDP + bn + tx * 3;
            if (mode == 0) {
                #pragma unroll
                for (int j = 0; j < 3; j++) C[row + j] = alpha * acc[i][j];
            } else {
                #pragma unroll
                for (int j = 0; j < 3; j++) C[row + j] = Dm[row + j] - acc[i][j];
            }
        }
        return;
    }

    // ---- syrk: write partial, last CTA of this pair reduces ----
    {
        float* P = g_Part + ((size_t)q * SZ + z) * TEL;
        #pragma unroll
        for (int i = 0; i < 3; i++)
            #pragma unroll
            for (int j = 0; j < 3; j++)
                P[(ty * 3 + i) * TMW + tx * 3 + j] = acc[i][j];
    }
    __threadfence();
    __syncthreads();
    if (tid == 0) {
        unsigned int t = atomicAdd(&g_cnt[q], 1u);
        slast = (t == SZ - 1) ? 1 : 0;
    }
    __syncthreads();
    if (!slast) return;

    #pragma unroll 1
    for (int g = 0; g < TEL / 256; g++) {
        const int idx = g * 256 + tid;
        float s = 0.f;
        #pragma unroll
        for (int zz = 0; zz < SZ; zz++)
            s += g_Part[((size_t)q * SZ + zz) * TEL + idx];
        const int m = idx / TMW, n = idx % TMW;
        C[(size_t)(bm + m) * HIDP + bn + n] = s;
        C[(size_t)(bn + n) * HIDP + bm + m] = s;
    }
    if (tid == 0) g_cnt[q] = 0;   // re-arm for graph replay
}

// ---------------- merged padded-operand builder ----------------
__global__ void build_ops(const float* __restrict__ Wx, const float* __restrict__ wy,
                          const float* __restrict__ Wq, const float* __restrict__ Wk,
                          const float* __restrict__ Wv,
                          float* __restrict__ Wxa, float* __restrict__ WqT,
                          float* __restrict__ WkT, float* __restrict__ WvP)
{
    const int idx = blockIdx.x * 256 + threadIdx.x;
    if (idx >= HIDP2) return;
    const int r = idx / HIDP, c = idx % HIDP;
    const bool in = (r < HID && c < HID);
    float wxa = 0.f;
    if (r < HID) {
        if (c < D_DIM) wxa = Wx[(size_t)r * D_DIM + c];
        else if (c == D_DIM) wxa = wy[r];
    }
    Wxa[idx] = wxa;
    WqT[idx] = in ? Wq[(size_t)c * HID + r] : 0.f;
    WkT[idx] = in ? Wk[(size_t)c * HID + r] : 0.f;
    WvP[idx] = in ? Wv[(size_t)r * HID + c] : 0.f;
}

// ---------------- vector tail (fp32 exact) ----------------
// uout[j] = uin[j] + sum_i A[i,j]*uin[i]
__global__ void gemv_t_add(const float* __restrict__ A, const float* __restrict__ uin,
                           float* __restrict__ uout)
{
    int j = blockIdx.x * 256 + threadIdx.x;
    if (j >= HID) return;
    float s = uin[j];
    #pragma unroll 8
    for (int i = 0; i < HID; i++) s += A[(size_t)i * HIDP + j] * uin[i];
    uout[j] = s;
}
__global__ void gemv_wx_t(const float* __restrict__ Wx, const float* __restrict__ u,
                          float* __restrict__ d)
{
    int j = blockIdx.x * 256 + threadIdx.x;
    if (j >= D_DIM) return;
    float s = 0.f;
    #pragma unroll 8
    for (int i = 0; i < HID; i++) s += Wx[(size_t)i * D_DIM + j] * u[i];
    d[j] = s;
}
__global__ void out_k(const float* __restrict__ Xs, const float* __restrict__ d,
                      float* __restrict__ out)
{
    int k = blockIdx.x * 8 + (threadIdx.x >> 5);
    int lane = threadIdx.x & 31;
    if (k >= KTEST) return;
    const float* row = Xs + (size_t)k * D_DIM;
    float s = 0.f;
    #pragma unroll 4
    for (int c = lane; c < D_DIM; c += 32) s += row[c] * d[c];
    #pragma unroll
    for (int o = 16; o > 0; o >>= 1) s += __shfl_xor_sync(0xFFFFFFFFu, s, o);
    if (lane == 0) out[k] = s;
}

// ---------------- host orchestration ----------------
static float* sym_addr(const void* sym) {
    void* p = nullptr;
    cudaGetSymbolAddress(&p, sym);
    return (float*)p;
}

extern "C" void kernel_launch(void* const* d_in, const int* in_sizes, int n_in,
                              void* d_out, int out_size)
{
    const float* X  = (const float*)d_in[0];
    const float* y  = (const float*)d_in[1];
    const float* Xs = (const float*)d_in[2];
    const float* Wx = (const float*)d_in[3];
    const float* wy = (const float*)d_in[4];
    const float* wo = (const float*)d_in[5];
    const float* Wk = (const float*)d_in[6];
    const float* Wq = (const float*)d_in[7];
    const float* Wv = (const float*)d_in[8];
    float* out = (float*)d_out;

    float* S   = sym_addr(g_S);
    float* Wxa = sym_addr(g_Wxa);
    float* WqT = sym_addr(g_WqT);
    float* WkT = sym_addr(g_WkT);
    float* WvP = sym_addr(g_WvP);
    float* F   = sym_addr(g_F);
    float* G   = sym_addr(g_G);
    float* T   = sym_addr(g_T);
    float* T2  = sym_addr(g_T2);
    float* A   = sym_addr(g_A);
    float* u   = sym_addr(g_u);
    float* dv  = sym_addr(g_d);

    const dim3 gG(NT12, NT12);         // 144 CTAs, one wave
    const dim3 gS(NPR, 1, SZ);         // 234 CTAs
    const int eb = (HIDP2 + 255) / 256;
    const float scale = 1.0f / (LDEPTH * (float)P_CTX);

    // 1) S = aug^T aug (symmetric, split-K=3, deterministic last-CTA reduce)
    gemm48<<<gS, 256>>>(X, 0, X, 0, y, S, nullptr, 1.f, 2);

    // 2) padded operands
    build_ops<<<eb, 256>>>(Wx, wy, Wq, Wk, Wv, Wxa, WqT, WkT, WvP);

    // 3) G0 = Wxa S Wxa^T ; F = Wq^T Wk (= E^T)
    gemm48<<<gG, 256>>>(Wxa, HIDP, S,   HIDP, nullptr, T, nullptr, 1.f, 0);
    gemm48<<<gG, 256>>>(T,   HIDP, Wxa, HIDP, nullptr, G, nullptr, 1.f, 0);
    gemm48<<<gG, 256>>>(WqT, HIDP, WkT, HIDP, nullptr, F, nullptr, 1.f, 0);

    // 4) layers: T = F·G (=(GE)^T); Al = scale·Wv·T^T; T2 = G - Al·G; G = T2 - T2·Al^T
    for (int l = 0; l < LDEPTH; l++) {
        float* Al = A + (size_t)l * HIDP2;
        gemm48<<<gG, 256>>>(F,   HIDP, G,  HIDP, nullptr, T,  nullptr, 1.f,   0);
        gemm48<<<gG, 256>>>(WvP, HIDP, T,  HIDP, nullptr, Al, nullptr, scale, 0);
        gemm48<<<gG, 256>>>(Al,  HIDP, G,  HIDP, nullptr, T2, G,       1.f,   1);
        gemm48<<<gG, 256>>>(T2,  HIDP, Al, HIDP, nullptr, G,  T2,      1.f,   1);
    }

    // 5) u = prod_{l=L-1..0} (I + A_l)^T  w_o   (first call reads wo directly)
    float* u0 = u;
    float* u1 = u + HID;
    for (int i = 0; i < LDEPTH; i++) {
        const int l = LDEPTH - 1 - i;
        const float* uin = (i == 0) ? wo : ((i & 1) ? u1 : u0);
        float* uout = (i & 1) ? u0 : u1;
        gemv_t_add<<<3, 256>>>(A + (size_t)l * HIDP2, uin, uout);
    }
    // final (i=7 odd) lands in u0

    // 6) d = Wx^T u ; out = X_star d
    gemv_wx_t<<<2, 256>>>(Wx, u0, dv);
    out_k<<<KTEST / 8, 256>>>(Xs, dv, out);
}

// round 7
// speedup vs baseline: 1.1493x; 1.1493x over previous
#include <cuda_runtime.h>
#include <cstdint>

// ---------------- problem constants ----------------
#define D_DIM  512
#define HID    513
#define P_CTX  8192
#define KTEST  2048
#define LDEPTH 8

#define NCTA    148
#define NT      9            // 64-tiles per matrix dim (576 = 9*64)
#define NTILES  81
#define KCHUNKS 33           // K = 528 (covers 513, chunks of 16)
#define PSTRIDE 4096         // floats per piece (64x64 tile)
#define TSTRIDE (3*PSTRIDE)  // up to 3 pieces per tile
#define MATSZ   (NTILES*TSTRIDE)

// syrk schedule: 45 symmetric tile-pairs x 512 chunks = 23040 chunk-jobs
#define SPAIR 45
#define SPC   5
#define SCALE_A (1.0f/65536.0f)   // 1/(L*P), exact

// matrix ids
#define mWXA 0
#define mWQT 1
#define mWKT 2
#define mWVP 3
#define mS   4
#define mF   5
#define mT   6
#define mT2  7
#define mG   8
#define mA0  9
#define NMAT 17

// ---------------- device storage ----------------
__device__ float g_M[NMAT][MATSZ];        // ~68 MB
__device__ float g_Spc[SPAIR*SPC*PSTRIDE];
__device__ float g_u[2][544];
__device__ float g_dv[544];
__device__ unsigned g_barCnt = 0;
__device__ unsigned g_barGen = 0;

// ---------------- static schedules (pure arithmetic) ----------------
// GEMM: 2673 chunks over 148 CTAs: CTA<9 get 19, rest 18
__device__ __forceinline__ int gsch_start(int c){ return c < 9 ? 19*c : 18*c + 9; }
__device__ __forceinline__ int gsch_len  (int c){ return c < 9 ? 19 : 18; }
__device__ __forceinline__ int gsch_cta  (int g){ return g < 171 ? g/19 : (g-9)/18; }
__device__ __forceinline__ int np_gemm   (int t){ return gsch_cta(t*33+32) - gsch_cta(t*33) + 1; }
// syrk: 23040 chunks over 148 CTAs: CTA<100 get 156, rest 155
__device__ __forceinline__ int ssch_start(int c){ return c < 100 ? 156*c : 15600 + 155*(c-100); }
__device__ __forceinline__ int ssch_len  (int c){ return c < 100 ? 156 : 155; }
__device__ __forceinline__ int ssch_cta  (int g){ return g < 15600 ? g/156 : 100 + (g-15600)/155; }
__device__ __forceinline__ int np_syrk   (int q){ return ssch_cta(q*512+511) - ssch_cta(q*512) + 1; }

// ---------------- grid-wide barrier (all 148 CTAs resident) ----------------
__device__ __forceinline__ void gsync() {
    __syncthreads();
    if (threadIdx.x == 0) {
        unsigned gen = *(volatile unsigned*)&g_barGen;
        __threadfence();
        if (atomicAdd(&g_barCnt, 1u) == NCTA - 1) {
            atomicExch(&g_barCnt, 0u);
            __threadfence();
            *(volatile unsigned*)&g_barGen = gen + 1u;
        } else {
            while (*(volatile unsigned*)&g_barGen == gen) { __nanosleep(64); }
        }
        __threadfence();
    }
    __syncthreads();
}

// ---------------- piece-summed float4 read ----------------
__device__ __forceinline__ float4 rd4(const float* base, int tile, int np, int off) {
    const float* p = base + (size_t)tile * TSTRIDE + off;
    float4 v = *(const float4*)p;
    #pragma unroll
    for (int q = 1; q < 3; q++) {
        if (q < np) {
            float4 w = *(const float4*)(p + q * PSTRIDE);
            v.x += w.x; v.y += w.y; v.z += w.z; v.w += w.w;
        }
    }
    return v;
}

// ---------------- one GEMM chunk-job (round-2 micro) ----------------
// acc(m,n) = sum over chunks [a0, a0+nc) of Atile(m,k)*Btile(n,k)
// writes piece `piece` of output tile; mode1: piece0 = Dm - acc, others = -acc
__device__ void gemm_job(const float* Ab, int multA, const float* Bb, int multB,
                         const float* Dmb, int multD, float* Cb,
                         int tile, int a0, int nc, int piece,
                         float alpha, int mode1, float* smA, float* smB)
{
    const int tid = threadIdx.x;
    const int am = tid >> 2, ak = (tid & 3) * 4;
    const int tx = tid & 15, ty = tid >> 4;
    const int tm = tile / NT, tn = tile % NT;

    float4 va, vb;
    auto ldg = [&](int ch) {
        const int k0 = (a0 + ch) * 16;
        const int tk = k0 >> 6;
        const int kl = (k0 & 63) + ak;
        const int ta = tm * NT + tk, tb = tn * NT + tk;
        va = rd4(Ab, ta, multA ? np_gemm(ta) : 1, am * 64 + kl);
        vb = rd4(Bb, tb, multB ? np_gemm(tb) : 1, am * 64 + kl);
    };
    auto sts = [&](int buf) {
        float* A = smA + buf * 1088;   // 16*68
        float* B = smB + buf * 1088;
        A[(ak+0)*68 + am] = va.x; A[(ak+1)*68 + am] = va.y;
        A[(ak+2)*68 + am] = va.z; A[(ak+3)*68 + am] = va.w;
        B[(ak+0)*68 + am] = vb.x; B[(ak+1)*68 + am] = vb.y;
        B[(ak+2)*68 + am] = vb.z; B[(ak+3)*68 + am] = vb.w;
    };

    float acc[4][4] = {};
    ldg(0); sts(0);
    __syncthreads();

    for (int ch = 0; ch < nc; ch++) {
        const int buf = ch & 1;
        const bool more = (ch + 1 < nc);
        if (more) ldg(ch + 1);
        const float* A = smA + buf * 1088;
        const float* B = smB + buf * 1088;
        #pragma unroll
        for (int kk = 0; kk < 16; kk++) {
            float4 a4 = *(const float4*)(A + kk * 68 + ty * 4);
            float4 b4 = *(const float4*)(B + kk * 68 + tx * 4);
            float a[4] = {a4.x, a4.y, a4.z, a4.w};
            float b[4] = {b4.x, b4.y, b4.z, b4.w};
            #pragma unroll
            for (int i = 0; i < 4; i++)
                #pragma unroll
                for (int j = 0; j < 4; j++)
                    acc[i][j] += a[i] * b[j];
        }
        if (more) {
            __syncthreads();
            sts(buf ^ 1);
            __syncthreads();
        }
    }

    float* Cp = Cb + (size_t)tile * TSTRIDE + piece * PSTRIDE;
    #pragma unroll
    for (int i = 0; i < 4; i++) {
        const int row = ty * 4 + i;
        float4 v = make_float4(acc[i][0], acc[i][1], acc[i][2], acc[i][3]);
        if (!mode1) {
            v.x *= alpha; v.y *= alpha; v.z *= alpha; v.w *= alpha;
        } else if (piece == 0) {
            float4 d = rd4(Dmb, tile, multD ? np_gemm(tile) : 1, row * 64 + tx * 4);
            v = make_float4(d.x - v.x, d.y - v.y, d.z - v.z, d.w - v.w);
        } else {
            v = make_float4(-v.x, -v.y, -v.z, -v.w);
        }
        *(float4*)(Cp + row * 64 + tx * 4) = v;
    }
    __syncthreads();
}

// ---------------- one syrk chunk-job ----------------
__device__ void syrk_job(const float* X, const float* yv,
                         int q, int a0, int nc, int piece,
                         float* smA, float* smB)
{
    const int tid = threadIdx.x;
    const int pl = tid >> 4, c4 = (tid & 15) * 4;
    const int tx = tid & 15, ty = tid >> 4;
    int ti = 0, rem = q;
    while (rem >= NT - ti) { rem -= NT - ti; ti++; }
    const int tj = ti + rem;
    const int bm = ti * 64, bn = tj * 64;

    float4 va, vb;
    auto aug4 = [&](int c0, int p) -> float4 {
        if (c0 < D_DIM) return *(const float4*)(X + (size_t)p * D_DIM + c0);
        float4 v = {0.f, 0.f, 0.f, 0.f};
        if (c0 == D_DIM) v.x = yv[p];
        return v;
    };
    auto ldg = [&](int ch) {
        const int p = (a0 + ch) * 16 + pl;
        va = aug4(bm + c4, p);
        vb = aug4(bn + c4, p);
    };
    auto sts = [&](int buf) {
        *(float4*)(smA + buf * 1088 + pl * 68 + c4) = va;
        *(float4*)(smB + buf * 1088 + pl * 68 + c4) = vb;
    };

    float acc[4][4] = {};
    ldg(0); sts(0);
    __syncthreads();
    for (int ch = 0; ch < nc; ch++) {
        const int buf = ch & 1;
        const bool more = (ch + 1 < nc);
        if (more) ldg(ch + 1);
        const float* A = smA + buf * 1088;
        const float* B = smB + buf * 1088;
        #pragma unroll
        for (int kk = 0; kk < 16; kk++) {
            float4 a4 = *(const float4*)(A + kk * 68 + ty * 4);
            float4 b4 = *(const float4*)(B + kk * 68 + tx * 4);
            float a[4] = {a4.x, a4.y, a4.z, a4.w};
            float b[4] = {b4.x, b4.y, b4.z, b4.w};
            #pragma unroll
            for (int i = 0; i < 4; i++)
                #pragma unroll
                for (int j = 0; j < 4; j++)
                    acc[i][j] += a[i] * b[j];
        }
        if (more) {
            __syncthreads();
            sts(buf ^ 1);
            __syncthreads();
        }
    }
    float* P = g_Spc + ((size_t)q * SPC + piece) * PSTRIDE;
    #pragma unroll
    for (int i = 0; i < 4; i++)
        *(float4*)(P + (ty * 4 + i) * 64 + tx * 4) =
            make_float4(acc[i][0], acc[i][1], acc[i][2], acc[i][3]);
    __syncthreads();
}

// ---------------- step descriptors ----------------
struct StepD { int a, b, dm, c; float alpha; };
__device__ __forceinline__ StepD get_step(int s) {
    if (s == 0) return {mWXA, mS,   -1, mT, 1.f};
    if (s == 1) return {mT,   mWXA, -1, mG, 1.f};
    if (s == 2) return {mWQT, mWKT, -1, mF, 1.f};
    const int l = (s - 3) >> 2, r = (s - 3) & 3;
    const int al = mA0 + l;
    if (r == 0) return {mF,   mG, -1, mT, 1.f};
    if (r == 1) return {mWVP, mT, -1, al, SCALE_A};
    if (r == 2) return {al,   mG, mG, mT2, 1.f};
    return {mT2, al, mT2, mG, 1.f};
}

// ================= the megakernel =================
__global__ __launch_bounds__(256) void mega(
    const float* __restrict__ X,  const float* __restrict__ yv,
    const float* __restrict__ Xs, const float* __restrict__ Wx,
    const float* __restrict__ wy, const float* __restrict__ wo,
    const float* __restrict__ Wk, const float* __restrict__ Wq,
    const float* __restrict__ Wv, float* __restrict__ out)
{
    __shared__ float smA[2*1088];
    __shared__ float smB[2*1088];
    const int tid  = threadIdx.x;
    const int cta  = blockIdx.x;
    const int gtid = cta * 256 + tid;
    const int lane = tid & 31;
    const int gw   = (cta << 3) + (tid >> 5);   // global warp 0..1183

    // -------- phase 0: dense operand conversion to tile layout --------
    for (int idx = gtid; idx < 4 * NTILES * PSTRIDE; idx += NCTA * 256) {
        const int m = idx / (NTILES * PSTRIDE);
        const int r4 = idx - m * (NTILES * PSTRIDE);
        const int t = r4 >> 12, e = r4 & 4095;
        const int r = (t / NT) * 64 + (e >> 6);
        const int cc = (t % NT) * 64 + (e & 63);
        const bool inb = (r < HID && cc < HID);
        float v = 0.f;
        if (m == 0) { if (r < HID) { if (cc < D_DIM) v = Wx[(size_t)r*D_DIM + cc];
                                     else if (cc == D_DIM) v = wy[r]; } }
        else if (m == 1) { if (inb) v = Wq[(size_t)cc*HID + r]; }
        else if (m == 2) { if (inb) v = Wk[(size_t)cc*HID + r]; }
        else             { if (inb) v = Wv[(size_t)r*HID + cc]; }
        g_M[m][(size_t)t * TSTRIDE + e] = v;
    }

    // -------- syrk (balanced chunk schedule) --------
    {
        const int gs = ssch_start(cta), len = ssch_len(cta);
        const int t0 = gs / 512, a0 = gs % 512;
        const int n1 = (512 - a0 < len) ? (512 - a0) : len;
        syrk_job(X, yv, t0, a0, n1, cta - ssch_cta(t0 * 512), smA, smB);
        if (len > n1)
            syrk_job(X, yv, t0 + 1, 0, len - n1, 0, smA, smB);
    }
    gsync();

    // -------- S consolidation (pieces -> dense tile layout, symmetric) ------
    for (int idx = gtid; idx < SPAIR * PSTRIDE; idx += NCTA * 256) {
        const int q = idx >> 12, e = idx & 4095;
        const int np = np_syrk(q);
        float s = 0.f;
        for (int p = 0; p < np; p++) s += g_Spc[((size_t)q * SPC + p) * PSTRIDE + e];
        int ti = 0, rem = q;
        while (rem >= NT - ti) { rem -= NT - ti; ti++; }
        const int tj = ti + rem;
        const int m = e >> 6, n = e & 63;
        g_M[mS][(size_t)(ti * NT + tj) * TSTRIDE + e] = s;
        g_M[mS][(size_t)(tj * NT + ti) * TSTRIDE + n * 64 + m] = s;
    }
    gsync();

    // -------- 35 GEMM steps --------
    const int ggs = gsch_start(cta), glen = gsch_len(cta);
    const int jt0 = ggs / 33, ja0 = ggs % 33;
    const int jn1 = (33 - ja0 < glen) ? (33 - ja0) : glen;
    const int p1 = cta - gsch_cta(jt0 * 33);

    for (int s = 0; s < 35; s++) {
        const StepD st = get_step(s);
        const float* Ab = g_M[st.a];
        const float* Bb = g_M[st.b];
        const float* Db = (st.dm >= 0) ? g_M[st.dm] : nullptr;
        float* Cb = g_M[st.c];
        const int mA = st.a >= mF, mB = st.b >= mF;
        const int mD = (st.dm >= 0) ? (st.dm >= mF) : 0;
        const int mode1 = (st.dm >= 0);
        gemm_job(Ab, mA, Bb, mB, Db, mD, Cb, jt0, ja0, jn1, p1, st.alpha, mode1, smA, smB);
        if (glen > jn1)
            gemm_job(Ab, mA, Bb, mB, Db, mD, Cb, jt0 + 1, 0, glen - jn1, 0, st.alpha, mode1, smA, smB);
        gsync();
    }

    // -------- u chain: u <- (I + A_l)^T u, l = 7..0 (warp per column j) -----
    for (int it = 0; it < 8; it++) {
        const float* Al = g_M[mA0 + (7 - it)];
        if (gw < HID) {
            const int j = gw, tj = j >> 6, jl = j & 63;
            float sacc = 0.f;
            for (int i = lane; i < HID; i += 32) {
                const int t = (i >> 6) * NT + tj;
                const int np = np_gemm(t);
                const float* p = Al + (size_t)t * TSTRIDE + (i & 63) * 64 + jl;
                float av = p[0];
                #pragma unroll
                for (int q = 1; q < 3; q++) if (q < np) av += p[q * PSTRIDE];
                const float uv = (it == 0) ? wo[i] : g_u[(it - 1) & 1][i];
                sacc += av * uv;
            }
            #pragma unroll
            for (int o = 16; o; o >>= 1) sacc += __shfl_xor_sync(0xFFFFFFFFu, sacc, o);
            if (lane == 0) {
                const float uj = (it == 0) ? wo[j] : g_u[(it - 1) & 1][j];
                g_u[it & 1][j] = uj + sacc;
            }
        }
        gsync();
    }
    // final u in g_u[1]

    // -------- d = Wx^T u --------
    if (gw < D_DIM) {
        const int j = gw;
        float sacc = 0.f;
        for (int i = lane; i < HID; i += 32) sacc += Wx[(size_t)i * D_DIM + j] * g_u[1][i];
        #pragma unroll
        for (int o = 16; o; o >>= 1) sacc += __shfl_xor_sync(0xFFFFFFFFu, sacc, o);
        if (lane == 0) g_dv[j] = sacc;
    }
    gsync();

    // -------- out[k] = Xs[k,:] . d --------
    for (int r = gw; r < KTEST; r += NCTA * 8) {
        const float* row = Xs + (size_t)r * D_DIM;
        float sacc = 0.f;
        #pragma unroll 4
        for (int c2 = lane; c2 < D_DIM; c2 += 32) sacc += row[c2] * g_dv[c2];
        #pragma unroll
        for (int o = 16; o; o >>= 1) sacc += __shfl_xor_sync(0xFFFFFFFFu, sacc, o);
        if (lane == 0) out[r] = sacc;
    }
}

// ---------------- host ----------------
extern "C" void kernel_launch(void* const* d_in, const int* in_sizes, int n_in,
                              void* d_out, int out_size)
{
    const float* X  = (const float*)d_in[0];
    const float* y  = (const float*)d_in[1];
    const float* Xs = (const float*)d_in[2];
    const float* Wx = (const float*)d_in[3];
    const float* wy = (const float*)d_in[4];
    const float* wo = (const float*)d_in[5];
    const float* Wk = (const float*)d_in[6];
    const float* Wq = (const float*)d_in[7];
    const float* Wv = (const float*)d_in[8];
    float* out = (float*)d_out;

    mega<<<NCTA, 256>>>(X, y, Xs, Wx, wy, wo, Wk, Wq, Wv, out);
}

// round 8
// speedup vs baseline: 1.1803x; 1.0270x over previous
#include <cuda_runtime.h>
#include <cstdint>

// ---------------- problem constants ----------------
#define D_DIM  512
#define HID    513
#define P_CTX  8192
#define KTEST  2048
#define LDEPTH 8

#define NCTA    148
#define NT      9            // 64-tiles per matrix dim (576 = 9*64)
#define NTILES  81
#define KCHUNKS 33           // K = 528 (covers 513, chunks of 16)
#define PSTRIDE 4096         // floats per piece (64x64 tile)
#define TSTRIDE (3*PSTRIDE)  // up to 3 pieces per tile
#define MATSZ   (NTILES*TSTRIDE)

// syrk schedule: 45 symmetric tile-pairs x 512 chunks = 23040 chunk-jobs
#define SPAIR 45
#define SPC   5
#define SCALE_A (1.0f/65536.0f)   // 1/(L*P), exact

// matrix ids
#define mWXA 0
#define mWQT 1
#define mWKT 2
#define mWVP 3
#define mS   4
#define mF   5
#define mT   6
#define mT2  7
#define mG   8
#define mA0  9
#define NMAT 17

// ---------------- device storage ----------------
__device__ float g_M[NMAT][MATSZ];        // ~68 MB
__device__ float g_Spc[SPAIR*SPC*PSTRIDE];
__device__ float g_u[2][544];
__device__ float g_dv[544];
__device__ unsigned g_barCnt = 0;
__device__ unsigned g_barGen = 0;

// ---------------- static schedules (pure arithmetic) ----------------
// GEMM: 2673 chunks over 148 CTAs: CTA<9 get 19, rest 18
__device__ __forceinline__ int gsch_start(int c){ return c < 9 ? 19*c : 18*c + 9; }
__device__ __forceinline__ int gsch_len  (int c){ return c < 9 ? 19 : 18; }
__device__ __forceinline__ int gsch_cta  (int g){ return g < 171 ? g/19 : (g-9)/18; }
__device__ __forceinline__ int np_gemm   (int t){ return gsch_cta(t*33+32) - gsch_cta(t*33) + 1; }
// syrk: 23040 chunks over 148 CTAs: CTA<100 get 156, rest 155
__device__ __forceinline__ int ssch_start(int c){ return c < 100 ? 156*c : 15600 + 155*(c-100); }
__device__ __forceinline__ int ssch_len  (int c){ return c < 100 ? 156 : 155; }
__device__ __forceinline__ int ssch_cta  (int g){ return g < 15600 ? g/156 : 100 + (g-15600)/155; }
__device__ __forceinline__ int np_syrk   (int q){ return ssch_cta(q*512+511) - ssch_cta(q*512) + 1; }

// ------- grid barrier: release/acquire protocol (no membar, gpu scope) -----
__device__ __forceinline__ void gsync() {
    __syncthreads();
    if (threadIdx.x == 0) {
        unsigned long long cntA, genA;
        asm("cvta.global.u64 %0, %1;" : "=l"(cntA) : "l"(&g_barCnt));
        asm("cvta.global.u64 %0, %1;" : "=l"(genA) : "l"(&g_barGen));
        unsigned gen;
        asm volatile("ld.acquire.gpu.global.u32 %0, [%1];" : "=r"(gen) : "l"(genA));
        unsigned prev;
        asm volatile("atom.release.gpu.global.add.u32 %0, [%1], 1;"
                     : "=r"(prev) : "l"(cntA));
        if (prev == NCTA - 1) {
            asm volatile("st.relaxed.gpu.global.u32 [%0], %1;" :: "l"(cntA), "r"(0u));
            asm volatile("st.release.gpu.global.u32 [%0], %1;" :: "l"(genA), "r"(gen + 1u));
        } else {
            unsigned g2;
            do {
                __nanosleep(32);
                asm volatile("ld.acquire.gpu.global.u32 %0, [%1];" : "=r"(g2) : "l"(genA));
            } while (g2 == gen);
        }
    }
    __syncthreads();
}

// ---------------- piece-summed float4 read ----------------
__device__ __forceinline__ float4 rd4(const float* base, int tile, int np, int off) {
    const float* p = base + (size_t)tile * TSTRIDE + off;
    float4 v = *(const float4*)p;
    #pragma unroll
    for (int q = 1; q < 3; q++) {
        if (q < np) {
            float4 w = *(const float4*)(p + q * PSTRIDE);
            v.x += w.x; v.y += w.y; v.z += w.z; v.w += w.w;
        }
    }
    return v;
}

// ---------------- one GEMM chunk-job (round-2 micro) ----------------
__device__ void gemm_job(const float* Ab, int multA, const float* Bb, int multB,
                         const float* Dmb, int multD, float* Cb,
                         int tile, int a0, int nc, int piece,
                         float alpha, int mode1, float* smA, float* smB)
{
    const int tid = threadIdx.x;
    const int am = tid >> 2, ak = (tid & 3) * 4;
    const int tx = tid & 15, ty = tid >> 4;
    const int tm = tile / NT, tn = tile % NT;

    float4 va, vb;
    auto ldg = [&](int ch) {
        const int k0 = (a0 + ch) * 16;
        const int tk = k0 >> 6;
        const int kl = (k0 & 63) + ak;
        const int ta = tm * NT + tk, tb = tn * NT + tk;
        va = rd4(Ab, ta, multA ? np_gemm(ta) : 1, am * 64 + kl);
        vb = rd4(Bb, tb, multB ? np_gemm(tb) : 1, am * 64 + kl);
    };
    auto sts = [&](int buf) {
        float* A = smA + buf * 1088;   // 16*68
        float* B = smB + buf * 1088;
        A[(ak+0)*68 + am] = va.x; A[(ak+1)*68 + am] = va.y;
        A[(ak+2)*68 + am] = va.z; A[(ak+3)*68 + am] = va.w;
        B[(ak+0)*68 + am] = vb.x; B[(ak+1)*68 + am] = vb.y;
        B[(ak+2)*68 + am] = vb.z; B[(ak+3)*68 + am] = vb.w;
    };

    float acc[4][4] = {};
    ldg(0); sts(0);
    __syncthreads();

    for (int ch = 0; ch < nc; ch++) {
        const int buf = ch & 1;
        const bool more = (ch + 1 < nc);
        if (more) ldg(ch + 1);
        const float* A = smA + buf * 1088;
        const float* B = smB + buf * 1088;
        #pragma unroll
        for (int kk = 0; kk < 16; kk++) {
            float4 a4 = *(const float4*)(A + kk * 68 + ty * 4);
            float4 b4 = *(const float4*)(B + kk * 68 + tx * 4);
            float a[4] = {a4.x, a4.y, a4.z, a4.w};
            float b[4] = {b4.x, b4.y, b4.z, b4.w};
            #pragma unroll
            for (int i = 0; i < 4; i++)
                #pragma unroll
                for (int j = 0; j < 4; j++)
                    acc[i][j] += a[i] * b[j];
        }
        if (more) {
            __syncthreads();
            sts(buf ^ 1);
            __syncthreads();
        }
    }

    float* Cp = Cb + (size_t)tile * TSTRIDE + piece * PSTRIDE;
    #pragma unroll
    for (int i = 0; i < 4; i++) {
        const int row = ty * 4 + i;
        float4 v = make_float4(acc[i][0], acc[i][1], acc[i][2], acc[i][3]);
        if (!mode1) {
            v.x *= alpha; v.y *= alpha; v.z *= alpha; v.w *= alpha;
        } else if (piece == 0) {
            float4 d = rd4(Dmb, tile, multD ? np_gemm(tile) : 1, row * 64 + tx * 4);
            v = make_float4(d.x - v.x, d.y - v.y, d.z - v.z, d.w - v.w);
        } else {
            v = make_float4(-v.x, -v.y, -v.z, -v.w);
        }
        *(float4*)(Cp + row * 64 + tx * 4) = v;
    }
    __syncthreads();
}

// ---------------- one syrk chunk-job ----------------
__device__ void syrk_job(const float* X, const float* yv,
                         int q, int a0, int nc, int piece,
                         float* smA, float* smB)
{
    const int tid = threadIdx.x;
    const int pl = tid >> 4, c4 = (tid & 15) * 4;
    const int tx = tid & 15, ty = tid >> 4;
    int ti = 0, rem = q;
    while (rem >= NT - ti) { rem -= NT - ti; ti++; }
    const int tj = ti + rem;
    const int bm = ti * 64, bn = tj * 64;

    float4 va, vb;
    auto aug4 = [&](int c0, int p) -> float4 {
        if (c0 < D_DIM) return *(const float4*)(X + (size_t)p * D_DIM + c0);
        float4 v = {0.f, 0.f, 0.f, 0.f};
        if (c0 == D_DIM) v.x = yv[p];
        return v;
    };
    auto ldg = [&](int ch) {
        const int p = (a0 + ch) * 16 + pl;
        va = aug4(bm + c4, p);
        vb = aug4(bn + c4, p);
    };
    auto sts = [&](int buf) {
        *(float4*)(smA + buf * 1088 + pl * 68 + c4) = va;
        *(float4*)(smB + buf * 1088 + pl * 68 + c4) = vb;
    };

    float acc[4][4] = {};
    ldg(0); sts(0);
    __syncthreads();
    for (int ch = 0; ch < nc; ch++) {
        const int buf = ch & 1;
        const bool more = (ch + 1 < nc);
        if (more) ldg(ch + 1);
        const float* A = smA + buf * 1088;
        const float* B = smB + buf * 1088;
        #pragma unroll
        for (int kk = 0; kk < 16; kk++) {
            float4 a4 = *(const float4*)(A + kk * 68 + ty * 4);
            float4 b4 = *(const float4*)(B + kk * 68 + tx * 4);
            float a[4] = {a4.x, a4.y, a4.z, a4.w};
            float b[4] = {b4.x, b4.y, b4.z, b4.w};
            #pragma unroll
            for (int i = 0; i < 4; i++)
                #pragma unroll
                for (int j = 0; j < 4; j++)
                    acc[i][j] += a[i] * b[j];
        }
        if (more) {
            __syncthreads();
            sts(buf ^ 1);
            __syncthreads();
        }
    }
    float* P = g_Spc + ((size_t)q * SPC + piece) * PSTRIDE;
    #pragma unroll
    for (int i = 0; i < 4; i++)
        *(float4*)(P + (ty * 4 + i) * 64 + tx * 4) =
            make_float4(acc[i][0], acc[i][1], acc[i][2], acc[i][3]);
    __syncthreads();
}

// ---------------- step descriptors ----------------
struct StepD { int a, b, dm, c; float alpha; };
__device__ __forceinline__ StepD get_step(int s) {
    if (s == 0) return {mWXA, mS,   -1, mT, 1.f};
    if (s == 1) return {mT,   mWXA, -1, mG, 1.f};
    if (s == 2) return {mWQT, mWKT, -1, mF, 1.f};
    const int l = (s - 3) >> 2, r = (s - 3) & 3;
    const int al = mA0 + l;
    if (r == 0) return {mF,   mG, -1, mT, 1.f};
    if (r == 1) return {mWVP, mT, -1, al, SCALE_A};
    if (r == 2) return {al,   mG, mG, mT2, 1.f};
    return {mT2, al, mT2, mG, 1.f};
}

// ================= the megakernel =================
__global__ __launch_bounds__(256) void mega(
    const float* __restrict__ X,  const float* __restrict__ yv,
    const float* __restrict__ Xs, const float* __restrict__ Wx,
    const float* __restrict__ wy, const float* __restrict__ wo,
    const float* __restrict__ Wk, const float* __restrict__ Wq,
    const float* __restrict__ Wv, float* __restrict__ out)
{
    __shared__ float smA[2*1088];
    __shared__ float smB[2*1088];
    const int tid  = threadIdx.x;
    const int cta  = blockIdx.x;
    const int gtid = cta * 256 + tid;
    const int lane = tid & 31;
    const int gw   = (cta << 3) + (tid >> 5);   // global warp 0..1183

    // -------- phase 0: dense operand conversion to tile layout --------
    for (int idx = gtid; idx < 4 * NTILES * PSTRIDE; idx += NCTA * 256) {
        const int m = idx / (NTILES * PSTRIDE);
        const int r4 = idx - m * (NTILES * PSTRIDE);
        const int t = r4 >> 12, e = r4 & 4095;
        const int r = (t / NT) * 64 + (e >> 6);
        const int cc = (t % NT) * 64 + (e & 63);
        const bool inb = (r < HID && cc < HID);
        float v = 0.f;
        if (m == 0) { if (r < HID) { if (cc < D_DIM) v = Wx[(size_t)r*D_DIM + cc];
                                     else if (cc == D_DIM) v = wy[r]; } }
        else if (m == 1) { if (inb) v = Wq[(size_t)cc*HID + r]; }
        else if (m == 2) { if (inb) v = Wk[(size_t)cc*HID + r]; }
        else             { if (inb) v = Wv[(size_t)r*HID + cc]; }
        g_M[m][(size_t)t * TSTRIDE + e] = v;
    }

    // -------- syrk (balanced chunk schedule) --------
    {
        const int gs = ssch_start(cta), len = ssch_len(cta);
        const int t0 = gs / 512, a0 = gs % 512;
        const int n1 = (512 - a0 < len) ? (512 - a0) : len;
        syrk_job(X, yv, t0, a0, n1, cta - ssch_cta(t0 * 512), smA, smB);
        if (len > n1)
            syrk_job(X, yv, t0 + 1, 0, len - n1, 0, smA, smB);
    }
    gsync();

    // -------- S consolidation (pieces -> dense tile layout, symmetric) ------
    for (int idx = gtid; idx < SPAIR * PSTRIDE; idx += NCTA * 256) {
        const int q = idx >> 12, e = idx & 4095;
        const int np = np_syrk(q);
        float s = 0.f;
        for (int p = 0; p < np; p++) s += g_Spc[((size_t)q * SPC + p) * PSTRIDE + e];
        int ti = 0, rem = q;
        while (rem >= NT - ti) { rem -= NT - ti; ti++; }
        const int tj = ti + rem;
        const int m = e >> 6, n = e & 63;
        g_M[mS][(size_t)(ti * NT + tj) * TSTRIDE + e] = s;
        g_M[mS][(size_t)(tj * NT + ti) * TSTRIDE + n * 64 + m] = s;
    }
    gsync();

    // -------- 35 GEMM steps --------
    const int ggs = gsch_start(cta), glen = gsch_len(cta);
    const int jt0 = ggs / 33, ja0 = ggs % 33;
    const int jn1 = (33 - ja0 < glen) ? (33 - ja0) : glen;
    const int p1 = cta - gsch_cta(jt0 * 33);

    for (int s = 0; s < 35; s++) {
        const StepD st = get_step(s);
        const float* Ab = g_M[st.a];
        const float* Bb = g_M[st.b];
        const float* Db = (st.dm >= 0) ? g_M[st.dm] : nullptr;
        float* Cb = g_M[st.c];
        const int mA = st.a >= mF, mB = st.b >= mF;
        const int mD = (st.dm >= 0) ? (st.dm >= mF) : 0;
        const int mode1 = (st.dm >= 0);
        gemm_job(Ab, mA, Bb, mB, Db, mD, Cb, jt0, ja0, jn1, p1, st.alpha, mode1, smA, smB);
        if (glen > jn1)
            gemm_job(Ab, mA, Bb, mB, Db, mD, Cb, jt0 + 1, 0, glen - jn1, 0, st.alpha, mode1, smA, smB);
        gsync();
    }

    // -------- u chain: u <- (I + A_l)^T u, l = 7..0 (warp per column j) -----
    for (int it = 0; it < 8; it++) {
        const float* Al = g_M[mA0 + (7 - it)];
        if (gw < HID) {
            const int j = gw, tj = j >> 6, jl = j & 63;
            float sacc = 0.f;
            for (int i = lane; i < HID; i += 32) {
                const int t = (i >> 6) * NT + tj;
                const int np = np_gemm(t);
                const float* p = Al + (size_t)t * TSTRIDE + (i & 63) * 64 + jl;
                float av = p[0];
                #pragma unroll
                for (int q = 1; q < 3; q++) if (q < np) av += p[q * PSTRIDE];
                const float uv = (it == 0) ? wo[i] : g_u[(it - 1) & 1][i];
                sacc += av * uv;
            }
            #pragma unroll
            for (int o = 16; o; o >>= 1) sacc += __shfl_xor_sync(0xFFFFFFFFu, sacc, o);
            if (lane == 0) {
                const float uj = (it == 0) ? wo[j] : g_u[(it - 1) & 1][j];
                g_u[it & 1][j] = uj + sacc;
            }
        }
        gsync();
    }
    // final u in g_u[1]

    // -------- d = Wx^T u --------
    if (gw < D_DIM) {
        const int j = gw;
        float sacc = 0.f;
        for (int i = lane; i < HID; i += 32) sacc += Wx[(size_t)i * D_DIM + j] * g_u[1][i];
        #pragma unroll
        for (int o = 16; o; o >>= 1) sacc += __shfl_xor_sync(0xFFFFFFFFu, sacc, o);
        if (lane == 0) g_dv[j] = sacc;
    }
    gsync();

    // -------- out[k] = Xs[k,:] . d --------
    for (int r = gw; r < KTEST; r += NCTA * 8) {
        const float* row = Xs + (size_t)r * D_DIM;
        float sacc = 0.f;
        #pragma unroll 4
        for (int c2 = lane; c2 < D_DIM; c2 += 32) sacc += row[c2] * g_dv[c2];
        #pragma unroll
        for (int o = 16; o; o >>= 1) sacc += __shfl_xor_sync(0xFFFFFFFFu, sacc, o);
        if (lane == 0) out[r] = sacc;
    }
}

// ---------------- host ----------------
extern "C" void kernel_launch(void* const* d_in, const int* in_sizes, int n_in,
                              void* d_out, int out_size)
{
    const float* X  = (const float*)d_in[0];
    const float* y  = (const float*)d_in[1];
    const float* Xs = (const float*)d_in[2];
    const float* Wx = (const float*)d_in[3];
    const float* wy = (const float*)d_in[4];
    const float* wo = (const float*)d_in[5];
    const float* Wk = (const float*)d_in[6];
    const float* Wq = (const float*)d_in[7];
    const float* Wv = (const float*)d_in[8];
    float* out = (float*)d_out;

    mega<<<NCTA, 256>>>(X, y, Xs, Wx, wy, wo, Wk, Wq, Wv, out);
}

// round 9
// speedup vs baseline: 1.3000x; 1.1015x over previous
#include <cuda_runtime.h>
#include <cstdint>

// ---------------- problem constants ----------------
#define D_DIM  512
#define HID    513
#define P_CTX  8192
#define KTEST  2048
#define LDEPTH 8

#define NCTA    148
#define NT      9            // 64-tiles per matrix dim (576 = 9*64)
#define NTILES  81
#define KCHUNKS 33           // K = 528 (covers 513, chunks of 16)
#define PSTRIDE 4096         // floats per piece (64x64 tile)
#define TSTRIDE (3*PSTRIDE)  // up to 3 pieces per tile
#define MATSZ   (NTILES*TSTRIDE)

#define SPAIR 45
#define SPC   5
#define SCALE_A (1.0f/65536.0f)

// dynamic smem: 4 tile buffers (2xA, 2xB) of 1088 floats + np tables
#define SM_BUF   1088
#define SM_NP    4352        // int region starts here (word index)
#define SMEM_BYTES ((4352 + 32) * 4)

// matrix ids
#define mWXA 0
#define mWQT 1
#define mWKT 2
#define mWVP 3
#define mS   4
#define mF   5
#define mT   6
#define mT2  7
#define mG   8
#define mA0  9
#define NMAT 17

// ---------------- device storage ----------------
__device__ float g_M[NMAT][MATSZ];
__device__ float g_Spc[SPAIR*SPC*PSTRIDE];
__device__ float g_u[2][544];
__device__ float g_dv[544];
__device__ unsigned g_barCnt = 0;
__device__ unsigned g_barGen = 0;

// ---------------- static schedules ----------------
__device__ __forceinline__ int gsch_start(int c){ return c < 9 ? 19*c : 18*c + 9; }
__device__ __forceinline__ int gsch_len  (int c){ return c < 9 ? 19 : 18; }
__device__ __forceinline__ int gsch_cta  (int g){ return g < 171 ? g/19 : (g-9)/18; }
__device__ __forceinline__ int np_gemm   (int t){ return gsch_cta(t*33+32) - gsch_cta(t*33) + 1; }
__device__ __forceinline__ int ssch_start(int c){ return c < 100 ? 156*c : 15600 + 155*(c-100); }
__device__ __forceinline__ int ssch_len  (int c){ return c < 100 ? 156 : 155; }
__device__ __forceinline__ int ssch_cta  (int g){ return g < 15600 ? g/156 : 100 + (g-15600)/155; }
__device__ __forceinline__ int np_syrk   (int q){ return ssch_cta(q*512+511) - ssch_cta(q*512) + 1; }

// ------- grid barrier: release/acquire, gpu scope -----
__device__ __forceinline__ void gsync() {
    __syncthreads();
    if (threadIdx.x == 0) {
        unsigned long long cntA, genA;
        asm("cvta.global.u64 %0, %1;" : "=l"(cntA) : "l"(&g_barCnt));
        asm("cvta.global.u64 %0, %1;" : "=l"(genA) : "l"(&g_barGen));
        unsigned gen;
        asm volatile("ld.acquire.gpu.global.u32 %0, [%1];" : "=r"(gen) : "l"(genA));
        unsigned prev;
        asm volatile("atom.release.gpu.global.add.u32 %0, [%1], 1;"
                     : "=r"(prev) : "l"(cntA));
        if (prev == NCTA - 1) {
            asm volatile("st.relaxed.gpu.global.u32 [%0], %1;" :: "l"(cntA), "r"(0u));
            asm volatile("st.release.gpu.global.u32 [%0], %1;" :: "l"(genA), "r"(gen + 1u));
        } else {
            unsigned g2;
            do {
                __nanosleep(32);
                asm volatile("ld.acquire.gpu.global.u32 %0, [%1];" : "=r"(g2) : "l"(genA));
            } while (g2 == gen);
        }
    }
    __syncthreads();
}

// ---------------- piece-summed float4 read ----------------
__device__ __forceinline__ float4 rd4(const float* base, int tile, int np, int off) {
    const float* p = base + (size_t)tile * TSTRIDE + off;
    float4 v = *(const float4*)p;
    if (np > 1) {
        float4 w = *(const float4*)(p + PSTRIDE);
        v.x += w.x; v.y += w.y; v.z += w.z; v.w += w.w;
        if (np > 2) {
            float4 u = *(const float4*)(p + 2 * PSTRIDE);
            v.x += u.x; v.y += u.y; v.z += u.z; v.w += u.w;
        }
    }
    return v;
}

// ---------------- one GEMM chunk-job ----------------
__device__ __forceinline__ void gemm_job(
    const float* Ab, int multA, const float* Bb, int multB,
    const float* Dmb, int multD, float* Cb,
    int tile, int a0, int nc, int piece, float alpha, int mode1)
{
    extern __shared__ float s_dyn[];
    int* s_np = (int*)(s_dyn + SM_NP);        // [0..8]=A, [9..17]=B, [18]=D
    const int tid = threadIdx.x;
    const int am = tid >> 2, ak = (tid & 3) * 4;
    const int tx = tid & 15, ty = tid >> 4;
    const int tm = tile / NT, tn = tile % NT;

    // hoist piece counts out of the hot loop (divisions once per job)
    if (tid < 9)       s_np[tid]      = multA ? np_gemm(tm * NT + tid) : 1;
    else if (tid < 18) s_np[tid]      = multB ? np_gemm(tn * NT + (tid - 9)) : 1;
    else if (tid == 18) s_np[18]      = multD ? np_gemm(tile) : 1;
    __syncthreads();

    float4 va, vb;
    auto ldg = [&](int ch) {
        const int k0 = (a0 + ch) * 16;
        const int tk = k0 >> 6;
        const int off = am * 64 + (k0 & 63) + ak;
        va = rd4(Ab, tm * NT + tk, s_np[tk], off);
        vb = rd4(Bb, tn * NT + tk, s_np[9 + tk], off);
    };
    auto sts = [&](int buf) {
        float* A = s_dyn + buf * SM_BUF;
        float* B = s_dyn + 2 * SM_BUF + buf * SM_BUF;
        A[(ak+0)*68 + am] = va.x; A[(ak+1)*68 + am] = va.y;
        A[(ak+2)*68 + am] = va.z; A[(ak+3)*68 + am] = va.w;
        B[(ak+0)*68 + am] = vb.x; B[(ak+1)*68 + am] = vb.y;
        B[(ak+2)*68 + am] = vb.z; B[(ak+3)*68 + am] = vb.w;
    };

    float acc[4][4] = {};
    ldg(0); sts(0);
    __syncthreads();

    for (int ch = 0; ch < nc; ch++) {
        const int buf = ch & 1;
        const bool more = (ch + 1 < nc);
        if (more) ldg(ch + 1);
        const float* A = s_dyn + buf * SM_BUF;
        const float* B = s_dyn + 2 * SM_BUF + buf * SM_BUF;
        #pragma unroll
        for (int kk = 0; kk < 16; kk++) {
            float4 a4 = *(const float4*)(A + kk * 68 + ty * 4);
            float4 b4 = *(const float4*)(B + kk * 68 + tx * 4);
            float a[4] = {a4.x, a4.y, a4.z, a4.w};
            float b[4] = {b4.x, b4.y, b4.z, b4.w};
            #pragma unroll
            for (int i = 0; i < 4; i++)
                #pragma unroll
                for (int j = 0; j < 4; j++)
                    acc[i][j] += a[i] * b[j];
        }
        if (more) {
            __syncthreads();
            sts(buf ^ 1);
            __syncthreads();
        }
    }

    float* Cp = Cb + (size_t)tile * TSTRIDE + piece * PSTRIDE;
    #pragma unroll
    for (int i = 0; i < 4; i++) {
        const int row = ty * 4 + i;
        float4 v = make_float4(acc[i][0], acc[i][1], acc[i][2], acc[i][3]);
        if (!mode1) {
            v.x *= alpha; v.y *= alpha; v.z *= alpha; v.w *= alpha;
        } else if (piece == 0) {
            float4 d = rd4(Dmb, tile, s_np[18], row * 64 + tx * 4);
            v = make_float4(d.x - v.x, d.y - v.y, d.z - v.z, d.w - v.w);
        } else {
            v = make_float4(-v.x, -v.y, -v.z, -v.w);
        }
        *(float4*)(Cp + row * 64 + tx * 4) = v;
    }
    __syncthreads();
}

// ---------------- one syrk chunk-job ----------------
__device__ __forceinline__ void syrk_job(
    const float* X, const float* yv, int q, int a0, int nc, int piece)
{
    extern __shared__ float s_dyn[];
    const int tid = threadIdx.x;
    const int pl = tid >> 4, c4 = (tid & 15) * 4;
    const int tx = tid & 15, ty = tid >> 4;
    int ti = 0, rem = q;
    while (rem >= NT - ti) { rem -= NT - ti; ti++; }
    const int tj = ti + rem;
    const int bm = ti * 64, bn = tj * 64;

    float4 va, vb;
    auto aug4 = [&](int c0, int p) -> float4 {
        if (c0 < D_DIM) return *(const float4*)(X + (size_t)p * D_DIM + c0);
        float4 v = {0.f, 0.f, 0.f, 0.f};
        if (c0 == D_DIM) v.x = yv[p];
        return v;
    };
    auto ldg = [&](int ch) {
        const int p = (a0 + ch) * 16 + pl;
        va = aug4(bm + c4, p);
        vb = aug4(bn + c4, p);
    };
    auto sts = [&](int buf) {
        *(float4*)(s_dyn + buf * SM_BUF + pl * 68 + c4) = va;
        *(float4*)(s_dyn + 2 * SM_BUF + buf * SM_BUF + pl * 68 + c4) = vb;
    };

    float acc[4][4] = {};
    ldg(0); sts(0);
    __syncthreads();
    for (int ch = 0; ch < nc; ch++) {
        const int buf = ch & 1;
        const bool more = (ch + 1 < nc);
        if (more) ldg(ch + 1);
        const float* A = s_dyn + buf * SM_BUF;
        const float* B = s_dyn + 2 * SM_BUF + buf * SM_BUF;
        #pragma unroll
        for (int kk = 0; kk < 16; kk++) {
            float4 a4 = *(const float4*)(A + kk * 68 + ty * 4);
            float4 b4 = *(const float4*)(B + kk * 68 + tx * 4);
            float a[4] = {a4.x, a4.y, a4.z, a4.w};
            float b[4] = {b4.x, b4.y, b4.z, b4.w};
            #pragma unroll
            for (int i = 0; i < 4; i++)
                #pragma unroll
                for (int j = 0; j < 4; j++)
                    acc[i][j] += a[i] * b[j];
        }
        if (more) {
            __syncthreads();
            sts(buf ^ 1);
            __syncthreads();
        }
    }
    float* P = g_Spc + ((size_t)q * SPC + piece) * PSTRIDE;
    #pragma unroll
    for (int i = 0; i < 4; i++)
        *(float4*)(P + (ty * 4 + i) * 64 + tx * 4) =
            make_float4(acc[i][0], acc[i][1], acc[i][2], acc[i][3]);
    __syncthreads();
}

// ---------------- step descriptors ----------------
struct StepD { int a, b, dm, c; float alpha; };
__device__ __forceinline__ StepD get_step(int s) {
    if (s == 0) return {mWXA, mS,   -1, mT, 1.f};
    if (s == 1) return {mT,   mWXA, -1, mG, 1.f};
    if (s == 2) return {mWQT, mWKT, -1, mF, 1.f};
    const int l = (s - 3) >> 2, r = (s - 3) & 3;
    const int al = mA0 + l;
    if (r == 0) return {mF,   mG, -1, mT, 1.f};
    if (r == 1) return {mWVP, mT, -1, al, SCALE_A};
    if (r == 2) return {al,   mG, mG, mT2, 1.f};
    return {mT2, al, mT2, mG, 1.f};
}

// ================= the megakernel =================
__global__ __launch_bounds__(256, 1) void mega(
    const float* __restrict__ X,  const float* __restrict__ yv,
    const float* __restrict__ Xs, const float* __restrict__ Wx,
    const float* __restrict__ wy, const float* __restrict__ wo,
    const float* __restrict__ Wk, const float* __restrict__ Wq,
    const float* __restrict__ Wv, float* __restrict__ out)
{
    extern __shared__ float s_dyn[];
    const int tid  = threadIdx.x;
    const int cta  = blockIdx.x;
    const int gtid = cta * 256 + tid;
    const int lane = tid & 31;
    const int gw   = (cta << 3) + (tid >> 5);

    // -------- phase 0: operand conversion to tile layout --------
    for (int idx = gtid; idx < 4 * NTILES * PSTRIDE; idx += NCTA * 256) {
        const int m = idx / (NTILES * PSTRIDE);
        const int r4 = idx - m * (NTILES * PSTRIDE);
        const int t = r4 >> 12, e = r4 & 4095;
        const int r = (t / NT) * 64 + (e >> 6);
        const int cc = (t % NT) * 64 + (e & 63);
        const bool inb = (r < HID && cc < HID);
        float v = 0.f;
        if (m == 0) { if (r < HID) { if (cc < D_DIM) v = Wx[(size_t)r*D_DIM + cc];
                                     else if (cc == D_DIM) v = wy[r]; } }
        else if (m == 1) { if (inb) v = Wq[(size_t)cc*HID + r]; }
        else if (m == 2) { if (inb) v = Wk[(size_t)cc*HID + r]; }
        else             { if (inb) v = Wv[(size_t)r*HID + cc]; }
        g_M[m][(size_t)t * TSTRIDE + e] = v;
    }

    // -------- syrk --------
    {
        const int gs = ssch_start(cta), len = ssch_len(cta);
        const int t0 = gs / 512, a0 = gs % 512;
        const int n1 = (512 - a0 < len) ? (512 - a0) : len;
        syrk_job(X, yv, t0, a0, n1, cta - ssch_cta(t0 * 512));
        if (len > n1)
            syrk_job(X, yv, t0 + 1, 0, len - n1, 0);
    }
    gsync();

    // -------- S consolidation --------
    for (int idx = gtid; idx < SPAIR * PSTRIDE; idx += NCTA * 256) {
        const int q = idx >> 12, e = idx & 4095;
        const int np = np_syrk(q);
        float s = 0.f;
        for (int p = 0; p < np; p++) s += g_Spc[((size_t)q * SPC + p) * PSTRIDE + e];
        int ti = 0, rem = q;
        while (rem >= NT - ti) { rem -= NT - ti; ti++; }
        const int tj = ti + rem;
        const int m = e >> 6, n = e & 63;
        g_M[mS][(size_t)(ti * NT + tj) * TSTRIDE + e] = s;
        g_M[mS][(size_t)(tj * NT + ti) * TSTRIDE + n * 64 + m] = s;
    }
    gsync();

    // -------- 35 GEMM steps --------
    const int ggs = gsch_start(cta), glen = gsch_len(cta);
    const int jt0 = ggs / 33, ja0 = ggs % 33;
    const int jn1 = (33 - ja0 < glen) ? (33 - ja0) : glen;
    const int p1 = cta - gsch_cta(jt0 * 33);

    for (int s = 0; s < 35; s++) {
        const StepD st = get_step(s);
        const float* Ab = g_M[st.a];
        const float* Bb = g_M[st.b];
        const float* Db = (st.dm >= 0) ? g_M[st.dm] : nullptr;
        float* Cb = g_M[st.c];
        const int mA = st.a >= mF, mB = st.b >= mF;
        const int mD = (st.dm >= 0) ? (st.dm >= mF) : 0;
        const int mode1 = (st.dm >= 0);
        gemm_job(Ab, mA, Bb, mB, Db, mD, Cb, jt0, ja0, jn1, p1, st.alpha, mode1);
        if (glen > jn1)
            gemm_job(Ab, mA, Bb, mB, Db, mD, Cb, jt0 + 1, 0, glen - jn1, 0, st.alpha, mode1);
        gsync();
    }

    // -------- u chain --------
    for (int it = 0; it < 8; it++) {
        const float* Al = g_M[mA0 + (7 - it)];
        if (gw < HID) {
            const int j = gw, tj = j >> 6, jl = j & 63;
            float sacc = 0.f;
            #pragma unroll 2
            for (int i = lane; i < HID; i += 32) {
                const int t = (i >> 6) * NT + tj;
                const int np = np_gemm(t);
                const float* p = Al + (size_t)t * TSTRIDE + (i & 63) * 64 + jl;
                float av = p[0];
                if (np > 1) av += p[PSTRIDE];
                if (np > 2) av += p[2 * PSTRIDE];
                const float uv = (it == 0) ? wo[i] : g_u[(it - 1) & 1][i];
                sacc += av * uv;
            }
            #pragma unroll
            for (int o = 16; o; o >>= 1) sacc += __shfl_xor_sync(0xFFFFFFFFu, sacc, o);
            if (lane == 0) {
                const float uj = (it == 0) ? wo[j] : g_u[(it - 1) & 1][j];
                g_u[it & 1][j] = uj + sacc;
            }
        }
        gsync();
    }

    // -------- d = Wx^T u --------
    if (gw < D_DIM) {
        const int j = gw;
        float sacc = 0.f;
        #pragma unroll 2
        for (int i = lane; i < HID; i += 32) sacc += Wx[(size_t)i * D_DIM + j] * g_u[1][i];
        #pragma unroll
        for (int o = 16; o; o >>= 1) sacc += __shfl_xor_sync(0xFFFFFFFFu, sacc, o);
        if (lane == 0) g_dv[j] = sacc;
    }
    gsync();

    // -------- out[k] = Xs[k,:] . d --------
    for (int r = gw; r < KTEST; r += NCTA * 8) {
        const float* row = Xs + (size_t)r * D_DIM;
        float sacc = 0.f;
        #pragma unroll 4
        for (int c2 = lane; c2 < D_DIM; c2 += 32) sacc += row[c2] * g_dv[c2];
        #pragma unroll
        for (int o = 16; o; o >>= 1) sacc += __shfl_xor_sync(0xFFFFFFFFu, sacc, o);
        if (lane == 0) out[r] = sacc;
    }
}

// ---------------- host ----------------
extern "C" void kernel_launch(void* const* d_in, const int* in_sizes, int n_in,
                              void* d_out, int out_size)
{
    const float* X  = (const float*)d_in[0];
    const float* y  = (const float*)d_in[1];
    const float* Xs = (const float*)d_in[2];
    const float* Wx = (const float*)d_in[3];
    const float* wy = (const float*)d_in[4];
    const float* wo = (const float*)d_in[5];
    const float* Wk = (const float*)d_in[6];
    const float* Wq = (const float*)d_in[7];
    const float* Wv = (const float*)d_in[8];
    float* out = (float*)d_out;

    mega<<<NCTA, 256, SMEM_BYTES>>>(X, y, Xs, Wx, wy, wo, Wk, Wq, Wv, out);
}

// round 10
// speedup vs baseline: 1.4506x; 1.1158x over previous
#include <cuda_runtime.h>
#include <cstdint>

// ---------------- problem constants ----------------
#define D_DIM  512
#define HID    513
#define P_CTX  8192
#define KTEST  2048
#define LDEPTH 8

#define NCTA    296          // 2 CTAs per SM
#define NT      9            // 64-tiles per matrix dim (576 = 9*64)
#define NTILES  81
#define KCHUNKS 33           // K = 528 (covers 513, chunks of 16)
#define PSTRIDE 4096         // floats per piece (64x64 tile)
#define NPIECE  5            // max pieces per tile (min job len 9 over 33 chunks)
#define TSTRIDE (NPIECE*PSTRIDE)
#define MATSZ   (NTILES*TSTRIDE)

#define SPAIR 45
#define SPC   8              // max syrk pieces (512 chunks / min len 77)
#define SCALE_A (1.0f/65536.0f)

// dynamic smem: 4 tile buffers (2xA, 2xB) of 1088 floats + np tables
#define SM_BUF   1088
#define SM_NP    4352
#define SMEM_BYTES ((4352 + 32) * 4)

// matrix ids
#define mWXA 0
#define mWQT 1
#define mWKT 2
#define mWVP 3
#define mS   4
#define mF   5
#define mT   6
#define mT2  7
#define mG   8
#define mA0  9
#define NMAT 17

// ---------------- device storage ----------------
__device__ float g_M[NMAT][MATSZ];         // ~113 MB
__device__ float g_Spc[SPAIR*SPC*PSTRIDE];
__device__ float g_u[2][544];
__device__ float g_dv[544];
__device__ unsigned g_barCnt = 0;
__device__ unsigned g_barGen = 0;

// ---------------- static schedules ----------------
// GEMM: 2673 chunks over 296 CTAs: CTA<9 get 10, rest 9
__device__ __forceinline__ int gsch_start(int c){ return c < 9 ? 10*c : 9*c + 9; }
__device__ __forceinline__ int gsch_len  (int c){ return c < 9 ? 10 : 9; }
__device__ __forceinline__ int gsch_cta  (int g){ return g < 90 ? g/10 : (g-9)/9; }
__device__ __forceinline__ int np_gemm   (int t){ return gsch_cta(t*33+32) - gsch_cta(t*33) + 1; }
// syrk: 23040 chunks over 296 CTAs: CTA<248 get 78, rest 77
__device__ __forceinline__ int ssch_start(int c){ return c < 248 ? 78*c : 19344 + 77*(c-248); }
__device__ __forceinline__ int ssch_len  (int c){ return c < 248 ? 78 : 77; }
__device__ __forceinline__ int ssch_cta  (int g){ return g < 19344 ? g/78 : 248 + (g-19344)/77; }
__device__ __forceinline__ int np_syrk   (int q){ return ssch_cta(q*512+511) - ssch_cta(q*512) + 1; }

// ------- grid barrier: release/acquire, gpu scope -----
__device__ __forceinline__ void gsync() {
    __syncthreads();
    if (threadIdx.x == 0) {
        unsigned long long cntA, genA;
        asm("cvta.global.u64 %0, %1;" : "=l"(cntA) : "l"(&g_barCnt));
        asm("cvta.global.u64 %0, %1;" : "=l"(genA) : "l"(&g_barGen));
        unsigned gen;
        asm volatile("ld.acquire.gpu.global.u32 %0, [%1];" : "=r"(gen) : "l"(genA));
        unsigned prev;
        asm volatile("atom.release.gpu.global.add.u32 %0, [%1], 1;"
                     : "=r"(prev) : "l"(cntA));
        if (prev == NCTA - 1) {
            asm volatile("st.relaxed.gpu.global.u32 [%0], %1;" :: "l"(cntA), "r"(0u));
            asm volatile("st.release.gpu.global.u32 [%0], %1;" :: "l"(genA), "r"(gen + 1u));
        } else {
            unsigned g2;
            do {
                __nanosleep(32);
                asm volatile("ld.acquire.gpu.global.u32 %0, [%1];" : "=r"(g2) : "l"(genA));
            } while (g2 == gen);
        }
    }
    __syncthreads();
}

// ---------------- piece-summed float4 read ----------------
__device__ __forceinline__ float4 rd4(const float* base, int tile, int np, int off) {
    const float* p = base + (size_t)tile * TSTRIDE + off;
    float4 v = *(const float4*)p;
    #pragma unroll
    for (int q = 1; q < NPIECE; q++) {
        if (q < np) {
            float4 w = *(const float4*)(p + q * PSTRIDE);
            v.x += w.x; v.y += w.y; v.z += w.z; v.w += w.w;
        }
    }
    return v;
}

// ---------------- one GEMM chunk-job ----------------
__device__ __forceinline__ void gemm_job(
    const float* Ab, int multA, const float* Bb, int multB,
    const float* Dmb, int multD, float* Cb,
    int tile, int a0, int nc, int piece, float alpha, int mode1)
{
    extern __shared__ float s_dyn[];
    int* s_np = (int*)(s_dyn + SM_NP);        // [0..8]=A, [9..17]=B, [18]=D
    const int tid = threadIdx.x;
    const int am = tid >> 2, ak = (tid & 3) * 4;
    const int tx = tid & 15, ty = tid >> 4;
    const int tm = tile / NT, tn = tile % NT;

    if (tid < 9)        s_np[tid] = multA ? np_gemm(tm * NT + tid) : 1;
    else if (tid < 18)  s_np[tid] = multB ? np_gemm(tn * NT + (tid - 9)) : 1;
    else if (tid == 18) s_np[18]  = multD ? np_gemm(tile) : 1;
    __syncthreads();

    float4 va, vb;
    auto ldg = [&](int ch) {
        const int k0 = (a0 + ch) * 16;
        const int tk = k0 >> 6;
        const int off = am * 64 + (k0 & 63) + ak;
        va = rd4(Ab, tm * NT + tk, s_np[tk], off);
        vb = rd4(Bb, tn * NT + tk, s_np[9 + tk], off);
    };
    auto sts = [&](int buf) {
        float* A = s_dyn + buf * SM_BUF;
        float* B = s_dyn + 2 * SM_BUF + buf * SM_BUF;
        A[(ak+0)*68 + am] = va.x; A[(ak+1)*68 + am] = va.y;
        A[(ak+2)*68 + am] = va.z; A[(ak+3)*68 + am] = va.w;
        B[(ak+0)*68 + am] = vb.x; B[(ak+1)*68 + am] = vb.y;
        B[(ak+2)*68 + am] = vb.z; B[(ak+3)*68 + am] = vb.w;
    };

    float acc[4][4] = {};
    ldg(0); sts(0);
    __syncthreads();

    for (int ch = 0; ch < nc; ch++) {
        const int buf = ch & 1;
        const bool more = (ch + 1 < nc);
        if (more) ldg(ch + 1);
        const float* A = s_dyn + buf * SM_BUF;
        const float* B = s_dyn + 2 * SM_BUF + buf * SM_BUF;
        #pragma unroll
        for (int kk = 0; kk < 16; kk++) {
            float4 a4 = *(const float4*)(A + kk * 68 + ty * 4);
            float4 b4 = *(const float4*)(B + kk * 68 + tx * 4);
            float a[4] = {a4.x, a4.y, a4.z, a4.w};
            float b[4] = {b4.x, b4.y, b4.z, b4.w};
            #pragma unroll
            for (int i = 0; i < 4; i++)
                #pragma unroll
                for (int j = 0; j < 4; j++)
                    acc[i][j] += a[i] * b[j];
        }
        if (more) {
            __syncthreads();
            sts(buf ^ 1);
            __syncthreads();
        }
    }

    float* Cp = Cb + (size_t)tile * TSTRIDE + piece * PSTRIDE;
    #pragma unroll
    for (int i = 0; i < 4; i++) {
        const int row = ty * 4 + i;
        float4 v = make_float4(acc[i][0], acc[i][1], acc[i][2], acc[i][3]);
        if (!mode1) {
            v.x *= alpha; v.y *= alpha; v.z *= alpha; v.w *= alpha;
        } else if (piece == 0) {
            float4 d = rd4(Dmb, tile, s_np[18], row * 64 + tx * 4);
            v = make_float4(d.x - v.x, d.y - v.y, d.z - v.z, d.w - v.w);
        } else {
            v = make_float4(-v.x, -v.y, -v.z, -v.w);
        }
        *(float4*)(Cp + row * 64 + tx * 4) = v;
    }
    __syncthreads();
}

// ---------------- one syrk chunk-job ----------------
__device__ __forceinline__ void syrk_job(
    const float* X, const float* yv, int q, int a0, int nc, int piece)
{
    extern __shared__ float s_dyn[];
    const int tid = threadIdx.x;
    const int pl = tid >> 4, c4 = (tid & 15) * 4;
    const int tx = tid & 15, ty = tid >> 4;
    int ti = 0, rem = q;
    while (rem >= NT - ti) { rem -= NT - ti; ti++; }
    const int tj = ti + rem;
    const int bm = ti * 64, bn = tj * 64;

    float4 va, vb;
    auto aug4 = [&](int c0, int p) -> float4 {
        if (c0 < D_DIM) return *(const float4*)(X + (size_t)p * D_DIM + c0);
        float4 v = {0.f, 0.f, 0.f, 0.f};
        if (c0 == D_DIM) v.x = yv[p];
        return v;
    };
    auto ldg = [&](int ch) {
        const int p = (a0 + ch) * 16 + pl;
        va = aug4(bm + c4, p);
        vb = aug4(bn + c4, p);
    };
    auto sts = [&](int buf) {
        *(float4*)(s_dyn + buf * SM_BUF + pl * 68 + c4) = va;
        *(float4*)(s_dyn + 2 * SM_BUF + buf * SM_BUF + pl * 68 + c4) = vb;
    };

    float acc[4][4] = {};
    ldg(0); sts(0);
    __syncthreads();
    for (int ch = 0; ch < nc; ch++) {
        const int buf = ch & 1;
        const bool more = (ch + 1 < nc);
        if (more) ldg(ch + 1);
        const float* A = s_dyn + buf * SM_BUF;
        const float* B = s_dyn + 2 * SM_BUF + buf * SM_BUF;
        #pragma unroll
        for (int kk = 0; kk < 16; kk++) {
            float4 a4 = *(const float4*)(A + kk * 68 + ty * 4);
            float4 b4 = *(const float4*)(B + kk * 68 + tx * 4);
            float a[4] = {a4.x, a4.y, a4.z, a4.w};
            float b[4] = {b4.x, b4.y, b4.z, b4.w};
            #pragma unroll
            for (int i = 0; i < 4; i++)
                #pragma unroll
                for (int j = 0; j < 4; j++)
                    acc[i][j] += a[i] * b[j];
        }
        if (more) {
            __syncthreads();
            sts(buf ^ 1);
            __syncthreads();
        }
    }
    float* P = g_Spc + ((size_t)q * SPC + piece) * PSTRIDE;
    #pragma unroll
    for (int i = 0; i < 4; i++)
        *(float4*)(P + (ty * 4 + i) * 64 + tx * 4) =
            make_float4(acc[i][0], acc[i][1], acc[i][2], acc[i][3]);
    __syncthreads();
}

// ---------------- step descriptors ----------------
struct StepD { int a, b, dm, c; float alpha; };
__device__ __forceinline__ StepD get_step(int s) {
    if (s == 0) return {mWXA, mS,   -1, mT, 1.f};
    if (s == 1) return {mT,   mWXA, -1, mG, 1.f};
    if (s == 2) return {mWQT, mWKT, -1, mF, 1.f};
    const int l = (s - 3) >> 2, r = (s - 3) & 3;
    const int al = mA0 + l;
    if (r == 0) return {mF,   mG, -1, mT, 1.f};
    if (r == 1) return {mWVP, mT, -1, al, SCALE_A};
    if (r == 2) return {al,   mG, mG, mT2, 1.f};
    return {mT2, al, mT2, mG, 1.f};
}

// ================= the megakernel =================
__global__ __launch_bounds__(256, 2) void mega(
    const float* __restrict__ X,  const float* __restrict__ yv,
    const float* __restrict__ Xs, const float* __restrict__ Wx,
    const float* __restrict__ wy, const float* __restrict__ wo,
    const float* __restrict__ Wk, const float* __restrict__ Wq,
    const float* __restrict__ Wv, float* __restrict__ out)
{
    extern __shared__ float s_dyn[];
    const int tid  = threadIdx.x;
    const int cta  = blockIdx.x;
    const int gtid = cta * 256 + tid;
    const int lane = tid & 31;
    const int gw   = (cta << 3) + (tid >> 5);

    // -------- phase 0: operand conversion to tile layout --------
    for (int idx = gtid; idx < 4 * NTILES * PSTRIDE; idx += NCTA * 256) {
        const int m = idx / (NTILES * PSTRIDE);
        const int r4 = idx - m * (NTILES * PSTRIDE);
        const int t = r4 >> 12, e = r4 & 4095;
        const int r = (t / NT) * 64 + (e >> 6);
        const int cc = (t % NT) * 64 + (e & 63);
        const bool inb = (r < HID && cc < HID);
        float v = 0.f;
        if (m == 0) { if (r < HID) { if (cc < D_DIM) v = Wx[(size_t)r*D_DIM + cc];
                                     else if (cc == D_DIM) v = wy[r]; } }
        else if (m == 1) { if (inb) v = Wq[(size_t)cc*HID + r]; }
        else if (m == 2) { if (inb) v = Wk[(size_t)cc*HID + r]; }
        else             { if (inb) v = Wv[(size_t)r*HID + cc]; }
        g_M[m][(size_t)t * TSTRIDE + e] = v;
    }

    // -------- syrk --------
    {
        const int gs = ssch_start(cta), len = ssch_len(cta);
        const int t0 = gs / 512, a0 = gs % 512;
        const int n1 = (512 - a0 < len) ? (512 - a0) : len;
        syrk_job(X, yv, t0, a0, n1, cta - ssch_cta(t0 * 512));
        if (len > n1)
            syrk_job(X, yv, t0 + 1, 0, len - n1, 0);
    }
    gsync();

    // -------- S consolidation --------
    for (int idx = gtid; idx < SPAIR * PSTRIDE; idx += NCTA * 256) {
        const int q = idx >> 12, e = idx & 4095;
        const int np = np_syrk(q);
        float s = 0.f;
        for (int p = 0; p < np; p++) s += g_Spc[((size_t)q * SPC + p) * PSTRIDE + e];
        int ti = 0, rem = q;
        while (rem >= NT - ti) { rem -= NT - ti; ti++; }
        const int tj = ti + rem;
        const int m = e >> 6, n = e & 63;
        g_M[mS][(size_t)(ti * NT + tj) * TSTRIDE + e] = s;
        g_M[mS][(size_t)(tj * NT + ti) * TSTRIDE + n * 64 + m] = s;
    }
    gsync();

    // -------- 35 GEMM steps --------
    const int ggs = gsch_start(cta), glen = gsch_len(cta);
    const int jt0 = ggs / 33, ja0 = ggs % 33;
    const int jn1 = (33 - ja0 < glen) ? (33 - ja0) : glen;
    const int p1 = cta - gsch_cta(jt0 * 33);

    for (int s = 0; s < 35; s++) {
        const StepD st = get_step(s);
        const float* Ab = g_M[st.a];
        const float* Bb = g_M[st.b];
        const float* Db = (st.dm >= 0) ? g_M[st.dm] : nullptr;
        float* Cb = g_M[st.c];
        const int mA = st.a >= mF, mB = st.b >= mF;
        const int mD = (st.dm >= 0) ? (st.dm >= mF) : 0;
        const int mode1 = (st.dm >= 0);
        gemm_job(Ab, mA, Bb, mB, Db, mD, Cb, jt0, ja0, jn1, p1, st.alpha, mode1);
        if (glen > jn1)
            gemm_job(Ab, mA, Bb, mB, Db, mD, Cb, jt0 + 1, 0, glen - jn1, 0, st.alpha, mode1);
        gsync();
    }

    // -------- u chain --------
    for (int it = 0; it < 8; it++) {
        const float* Al = g_M[mA0 + (7 - it)];
        if (gw < HID) {
            const int j = gw, tj = j >> 6, jl = j & 63;
            float sacc = 0.f;
            #pragma unroll 2
            for (int i = lane; i < HID; i += 32) {
                const int t = (i >> 6) * NT + tj;
                const int np = np_gemm(t);
                const float* p = Al + (size_t)t * TSTRIDE + (i & 63) * 64 + jl;
                float av = p[0];
                #pragma unroll
                for (int q2 = 1; q2 < NPIECE; q2++)
                    if (q2 < np) av += p[q2 * PSTRIDE];
                const float uv = (it == 0) ? wo[i] : g_u[(it - 1) & 1][i];
                sacc += av * uv;
            }
            #pragma unroll
            for (int o = 16; o; o >>= 1) sacc += __shfl_xor_sync(0xFFFFFFFFu, sacc, o);
            if (lane == 0) {
                const float uj = (it == 0) ? wo[j] : g_u[(it - 1) & 1][j];
                g_u[it & 1][j] = uj + sacc;
            }
        }
        gsync();
    }

    // -------- d = Wx^T u --------
    if (gw < D_DIM) {
        const int j = gw;
        float sacc = 0.f;
        #pragma unroll 2
        for (int i = lane; i < HID; i += 32) sacc += Wx[(size_t)i * D_DIM + j] * g_u[1][i];
        #pragma unroll
        for (int o = 16; o; o >>= 1) sacc += __shfl_xor_sync(0xFFFFFFFFu, sacc, o);
        if (lane == 0) g_dv[j] = sacc;
    }
    gsync();

    // -------- out[k] = Xs[k,:] . d --------
    for (int r = gw; r < KTEST; r += NCTA * 8) {
        const float* row = Xs + (size_t)r * D_DIM;
        float sacc = 0.f;
        #pragma unroll 4
        for (int c2 = lane; c2 < D_DIM; c2 += 32) sacc += row[c2] * g_dv[c2];
        #pragma unroll
        for (int o = 16; o; o >>= 1) sacc += __shfl_xor_sync(0xFFFFFFFFu, sacc, o);
        if (lane == 0) out[r] = sacc;
    }
}

// ---------------- host ----------------
extern "C" void kernel_launch(void* const* d_in, const int* in_sizes, int n_in,
                              void* d_out, int out_size)
{
    const float* X  = (const float*)d_in[0];
    const float* y  = (const float*)d_in[1];
    const float* Xs = (const float*)d_in[2];
    const float* Wx = (const float*)d_in[3];
    const float* wy = (const float*)d_in[4];
    const float* wo = (const float*)d_in[5];
    const float* Wk = (const float*)d_in[6];
    const float* Wq = (const float*)d_in[7];
    const float* Wv = (const float*)d_in[8];
    float* out = (float*)d_out;

    mega<<<NCTA, 256, SMEM_BYTES>>>(X, y, Xs, Wx, wy, wo, Wk, Wq, Wv, out);
}